// round 8
// baseline (speedup 1.0000x reference)
#include <cuda_runtime.h>
#include <cuda_fp16.h>
#include <cstdint>

#define N_NODES 100000
#define N_EDGES 1638400
#define IN_F    128
#define OUT_F   64
#define NUM_RELS 8
#define COLS    (NUM_RELS * OUT_F)   // 512
#define SCAN_BLOCKS ((N_NODES + 255) / 256)   // 391

// Scratch: xw[r][n][o] in fp16, layout ((r*N + n)*64 + o). 102.4 MB.
__device__ __half g_xw[(size_t)NUM_RELS * N_NODES * OUT_F];

// CSR-by-destination scratch
__device__ int g_cnt[N_NODES];
__device__ int g_off[N_NODES + 1];
__device__ int g_cursor[N_NODES];
__device__ int g_bsum[512];
__device__ int g_perm[N_EDGES];     // packed rel*N_NODES + src, grouped by dst

__device__ __forceinline__ uint32_t cvt_tf32(float f) {
    uint32_t r;
    asm("cvt.rna.tf32.f32 %0, %1;" : "=r"(r) : "f"(f));
    return r;
}

// ---------------------------------------------------------------------------
// CSR build: zero counters -> histogram -> 3-step scan -> fill
// ---------------------------------------------------------------------------
__global__ void init_cnt_kernel() {
    int i = blockIdx.x * blockDim.x + threadIdx.x;
    if (i < N_NODES) g_cnt[i] = 0;
}

__global__ void hist_kernel(const int* __restrict__ edst) {
    int e = blockIdx.x * blockDim.x + threadIdx.x;
    if (e < N_EDGES) atomicAdd(&g_cnt[edst[e]], 1);
}

__global__ void scan1_kernel() {
    __shared__ int s[256];
    int tid = threadIdx.x;
    int i = blockIdx.x * 256 + tid;
    int v = (i < N_NODES) ? g_cnt[i] : 0;
    s[tid] = v;
    __syncthreads();
#pragma unroll
    for (int d = 1; d < 256; d <<= 1) {
        int t = (tid >= d) ? s[tid - d] : 0;
        __syncthreads();
        s[tid] += t;
        __syncthreads();
    }
    if (i < N_NODES) g_off[i] = s[tid] - v;      // block-local exclusive
    if (tid == 255) g_bsum[blockIdx.x] = s[255];
}

__global__ void scan2_kernel() {
    __shared__ int s[512];
    int tid = threadIdx.x;
    int v = (tid < SCAN_BLOCKS) ? g_bsum[tid] : 0;
    s[tid] = v;
    __syncthreads();
#pragma unroll
    for (int d = 1; d < 512; d <<= 1) {
        int t = (tid >= d) ? s[tid - d] : 0;
        __syncthreads();
        s[tid] += t;
        __syncthreads();
    }
    if (tid < SCAN_BLOCKS) g_bsum[tid] = s[tid] - v;   // exclusive
}

__global__ void scan3_kernel() {
    int i = blockIdx.x * 256 + threadIdx.x;
    if (i < N_NODES) {
        int o = g_off[i] + g_bsum[blockIdx.x];
        g_off[i] = o;
        g_cursor[i] = o;
    }
    if (i == 0) g_off[N_NODES] = N_EDGES;
}

__global__ void fill_kernel(const int* __restrict__ esrc,
                            const int* __restrict__ edst,
                            const int* __restrict__ etyp) {
    int e = blockIdx.x * blockDim.x + threadIdx.x;
    if (e < N_EDGES) {
        int d = edst[e];
        int pos = atomicAdd(&g_cursor[d], 1);
        g_perm[pos] = etyp[e] * N_NODES + esrc[e];
    }
}

// ---------------------------------------------------------------------------
// tf32 mma.sync GEMM: C[n][c] = sum_k feat[n][k] * W[r][o][k], c = r*64+o.
// CTA tile 128x128, BK=32, 256 threads = 8 warps (2 x 4), warp tile 64x32.
// Epilogue stores fp16.
// ---------------------------------------------------------------------------
__global__ __launch_bounds__(256, 2)
void gemm_mma_kernel(const float* __restrict__ feat, const float* __restrict__ W) {
    __shared__ uint32_t As[32][136];
    __shared__ uint32_t Bs[32][136];

    const int bm = blockIdx.x * 128;
    const int bc = blockIdx.y * 128;
    const int tid = threadIdx.x;
    const int wid = tid >> 5;
    const int lane = tid & 31;
    const int g = lane >> 2;
    const int t = lane & 3;
    const int warp_m = (wid & 1) * 64;
    const int warp_n = (wid >> 1) * 32;

    float acc[4][4][4];
#pragma unroll
    for (int i = 0; i < 4; i++)
#pragma unroll
        for (int j = 0; j < 4; j++)
#pragma unroll
            for (int c = 0; c < 4; c++) acc[i][j][c] = 0.f;

    for (int k0 = 0; k0 < IN_F; k0 += 32) {
#pragma unroll
        for (int j = tid; j < 1024; j += 256) {
            int row = j >> 3;
            int kq  = j & 7;
            int n   = bm + row;
            float4 v = make_float4(0.f, 0.f, 0.f, 0.f);
            if (n < N_NODES)
                v = *reinterpret_cast<const float4*>(feat + (size_t)n * IN_F + k0 + kq * 4);
            As[kq * 4 + 0][row] = cvt_tf32(v.x);
            As[kq * 4 + 1][row] = cvt_tf32(v.y);
            As[kq * 4 + 2][row] = cvt_tf32(v.z);
            As[kq * 4 + 3][row] = cvt_tf32(v.w);
        }
#pragma unroll
        for (int j = tid; j < 1024; j += 256) {
            int col = j >> 3;
            int kq  = j & 7;
            int c   = bc + col;
            int r   = c >> 6;
            int o   = c & 63;
            float4 v = *reinterpret_cast<const float4*>(
                W + ((size_t)r * OUT_F + o) * IN_F + k0 + kq * 4);
            Bs[kq * 4 + 0][col] = cvt_tf32(v.x);
            Bs[kq * 4 + 1][col] = cvt_tf32(v.y);
            Bs[kq * 4 + 2][col] = cvt_tf32(v.z);
            Bs[kq * 4 + 3][col] = cvt_tf32(v.w);
        }
        __syncthreads();

#pragma unroll
        for (int ks = 0; ks < 4; ks++) {
            const int kb = ks * 8;
            uint32_t af[4][4];
#pragma unroll
            for (int mt = 0; mt < 4; mt++) {
                int row = warp_m + mt * 16 + g;
                af[mt][0] = As[kb + t][row];
                af[mt][1] = As[kb + t][row + 8];
                af[mt][2] = As[kb + t + 4][row];
                af[mt][3] = As[kb + t + 4][row + 8];
            }
            uint32_t bf[4][2];
#pragma unroll
            for (int nt = 0; nt < 4; nt++) {
                int col = warp_n + nt * 8 + g;
                bf[nt][0] = Bs[kb + t][col];
                bf[nt][1] = Bs[kb + t + 4][col];
            }
#pragma unroll
            for (int mt = 0; mt < 4; mt++)
#pragma unroll
                for (int nt = 0; nt < 4; nt++) {
                    asm volatile(
                        "mma.sync.aligned.m16n8k8.row.col.f32.tf32.tf32.f32 "
                        "{%0,%1,%2,%3}, {%4,%5,%6,%7}, {%8,%9}, {%0,%1,%2,%3};"
                        : "+f"(acc[mt][nt][0]), "+f"(acc[mt][nt][1]),
                          "+f"(acc[mt][nt][2]), "+f"(acc[mt][nt][3])
                        : "r"(af[mt][0]), "r"(af[mt][1]), "r"(af[mt][2]), "r"(af[mt][3]),
                          "r"(bf[nt][0]), "r"(bf[nt][1]));
                }
        }
        __syncthreads();
    }

    // Store fp16: c0=C[g][2t] c1=C[g][2t+1] (one half2 = 4B), rows g and g+8.
#pragma unroll
    for (int mt = 0; mt < 4; mt++) {
#pragma unroll
        for (int nt = 0; nt < 4; nt++) {
            int col = bc + warp_n + nt * 8 + t * 2;
            int rel = col >> 6;
            int o   = col & 63;
            int row0 = bm + warp_m + mt * 16 + g;
            if (row0 < N_NODES) {
                __half2* p = reinterpret_cast<__half2*>(
                    g_xw + ((size_t)rel * N_NODES + row0) * OUT_F + o);
                *p = __floats2half2_rn(acc[mt][nt][0], acc[mt][nt][1]);
            }
            int row1 = row0 + 8;
            if (row1 < N_NODES) {
                __half2* p = reinterpret_cast<__half2*>(
                    g_xw + ((size_t)rel * N_NODES + row1) * OUT_F + o);
                *p = __floats2half2_rn(acc[mt][nt][2], acc[mt][nt][3]);
            }
        }
    }
}

// ---------------------------------------------------------------------------
// Reduce: one warp per destination node. Lane l owns output cols 2l, 2l+1
// (one half2 = 4B; warp reads a full 128B row per step). fp32 accumulate.
// ---------------------------------------------------------------------------
__global__ __launch_bounds__(256)
void reduce_kernel(float* __restrict__ out) {
    int warp = (blockIdx.x * 256 + threadIdx.x) >> 5;   // node id, exact cover
    int lane = threadIdx.x & 31;
    int beg = g_off[warp];
    int end = g_off[warp + 1];

    const __half2* xw2 = reinterpret_cast<const __half2*>(g_xw);
    float2 acc = make_float2(0.f, 0.f);
    int j = beg;
    for (; j + 8 <= end; j += 8) {
        float2 v[8];
#pragma unroll
        for (int u = 0; u < 8; u++) {
            int p = g_perm[j + u];
            v[u] = __half22float2(xw2[(size_t)p * (OUT_F / 2) + lane]);
        }
#pragma unroll
        for (int u = 0; u < 8; u++) { acc.x += v[u].x; acc.y += v[u].y; }
    }
    for (; j < end; j++) {
        int p = g_perm[j];
        float2 v = __half22float2(xw2[(size_t)p * (OUT_F / 2) + lane]);
        acc.x += v.x; acc.y += v.y;
    }
    *reinterpret_cast<float2*>(out + (size_t)warp * OUT_F + lane * 2) = acc;
}

extern "C" void kernel_launch(void* const* d_in, const int* in_sizes, int n_in,
                              void* d_out, int out_size) {
    const float* feat = (const float*)d_in[0];
    const float* W    = (const float*)d_in[1];
    const int* esrc   = (const int*)d_in[2];
    const int* edst   = (const int*)d_in[3];
    const int* etyp   = (const int*)d_in[4];
    float* out        = (float*)d_out;

    const int nb_node = (N_NODES + 255) / 256;   // 391
    const int nb_edge = (N_EDGES + 255) / 256;   // 6400

    // CSR build by destination
    init_cnt_kernel<<<nb_node, 256>>>();
    hist_kernel<<<nb_edge, 256>>>(edst);
    scan1_kernel<<<SCAN_BLOCKS, 256>>>();
    scan2_kernel<<<1, 512>>>();
    scan3_kernel<<<SCAN_BLOCKS, 256>>>();
    fill_kernel<<<nb_edge, 256>>>(esrc, edst, etyp);

    // xw[r][n][o] = feat @ W[r]^T via tf32 mma.sync (fp16 store)
    dim3 ggrid((N_NODES + 127) / 128, COLS / 128);
    gemm_mma_kernel<<<ggrid, 256>>>(feat, W);

    // Gather + register reduce per destination node (writes every output elem)
    reduce_kernel<<<(N_NODES * 32) / 256, 256>>>(out);
}

// round 9
// speedup vs baseline: 1.0231x; 1.0231x over previous
#include <cuda_runtime.h>
#include <cuda_fp16.h>
#include <cstdint>

#define N_NODES 100000
#define N_EDGES 1638400
#define IN_F    128
#define OUT_F   64
#define NUM_RELS 8
#define COLS    (NUM_RELS * OUT_F)   // 512
#define SCAN_BLOCKS ((N_NODES + 255) / 256)   // 391

// Scratch: xw[r][n][o] in fp16, layout ((r*N + n)*64 + o). 102.4 MB.
__device__ __half g_xw[(size_t)NUM_RELS * N_NODES * OUT_F];

// CSR-by-destination scratch
__device__ int g_cnt[N_NODES];
__device__ int g_off[N_NODES + 1];
__device__ int g_cursor[N_NODES];
__device__ int g_bsum[512];
__device__ int g_perm[N_EDGES];     // packed rel*N_NODES + src, grouped by dst

__device__ __forceinline__ uint32_t cvt_tf32(float f) {
    uint32_t r;
    asm("cvt.rna.tf32.f32 %0, %1;" : "=r"(r) : "f"(f));
    return r;
}

// ---------------------------------------------------------------------------
// CSR build: zero counters -> histogram -> 3-step scan -> fill
// ---------------------------------------------------------------------------
__global__ void init_cnt_kernel() {
    int i = blockIdx.x * blockDim.x + threadIdx.x;
    if (i < N_NODES) g_cnt[i] = 0;
}

__global__ void hist_kernel(const int* __restrict__ edst) {
    int e = blockIdx.x * blockDim.x + threadIdx.x;
    if (e < N_EDGES) atomicAdd(&g_cnt[edst[e]], 1);
}

__global__ void scan1_kernel() {
    __shared__ int s[256];
    int tid = threadIdx.x;
    int i = blockIdx.x * 256 + tid;
    int v = (i < N_NODES) ? g_cnt[i] : 0;
    s[tid] = v;
    __syncthreads();
#pragma unroll
    for (int d = 1; d < 256; d <<= 1) {
        int t = (tid >= d) ? s[tid - d] : 0;
        __syncthreads();
        s[tid] += t;
        __syncthreads();
    }
    if (i < N_NODES) g_off[i] = s[tid] - v;      // block-local exclusive
    if (tid == 255) g_bsum[blockIdx.x] = s[255];
}

__global__ void scan2_kernel() {
    __shared__ int s[512];
    int tid = threadIdx.x;
    int v = (tid < SCAN_BLOCKS) ? g_bsum[tid] : 0;
    s[tid] = v;
    __syncthreads();
#pragma unroll
    for (int d = 1; d < 512; d <<= 1) {
        int t = (tid >= d) ? s[tid - d] : 0;
        __syncthreads();
        s[tid] += t;
        __syncthreads();
    }
    if (tid < SCAN_BLOCKS) g_bsum[tid] = s[tid] - v;   // exclusive
}

__global__ void scan3_kernel() {
    int i = blockIdx.x * 256 + threadIdx.x;
    if (i < N_NODES) {
        int o = g_off[i] + g_bsum[blockIdx.x];
        g_off[i] = o;
        g_cursor[i] = o;
    }
    if (i == 0) g_off[N_NODES] = N_EDGES;
}

__global__ void fill_kernel(const int* __restrict__ esrc,
                            const int* __restrict__ edst,
                            const int* __restrict__ etyp) {
    int e = blockIdx.x * blockDim.x + threadIdx.x;
    if (e < N_EDGES) {
        int d = edst[e];
        int pos = atomicAdd(&g_cursor[d], 1);
        g_perm[pos] = etyp[e] * N_NODES + esrc[e];
    }
}

// ---------------------------------------------------------------------------
// tf32 mma.sync GEMM: C[n][c] = sum_k feat[n][k] * W[r][o][k], c = r*64+o.
// CTA tile 128x128, BK=32, 256 threads = 8 warps (2 x 4), warp tile 64x32.
// Epilogue stores fp16.
// ---------------------------------------------------------------------------
__global__ __launch_bounds__(256, 2)
void gemm_mma_kernel(const float* __restrict__ feat, const float* __restrict__ W) {
    __shared__ uint32_t As[32][136];
    __shared__ uint32_t Bs[32][136];

    const int bm = blockIdx.x * 128;
    const int bc = blockIdx.y * 128;
    const int tid = threadIdx.x;
    const int wid = tid >> 5;
    const int lane = tid & 31;
    const int g = lane >> 2;
    const int t = lane & 3;
    const int warp_m = (wid & 1) * 64;
    const int warp_n = (wid >> 1) * 32;

    float acc[4][4][4];
#pragma unroll
    for (int i = 0; i < 4; i++)
#pragma unroll
        for (int j = 0; j < 4; j++)
#pragma unroll
            for (int c = 0; c < 4; c++) acc[i][j][c] = 0.f;

    for (int k0 = 0; k0 < IN_F; k0 += 32) {
#pragma unroll
        for (int j = tid; j < 1024; j += 256) {
            int row = j >> 3;
            int kq  = j & 7;
            int n   = bm + row;
            float4 v = make_float4(0.f, 0.f, 0.f, 0.f);
            if (n < N_NODES)
                v = *reinterpret_cast<const float4*>(feat + (size_t)n * IN_F + k0 + kq * 4);
            As[kq * 4 + 0][row] = cvt_tf32(v.x);
            As[kq * 4 + 1][row] = cvt_tf32(v.y);
            As[kq * 4 + 2][row] = cvt_tf32(v.z);
            As[kq * 4 + 3][row] = cvt_tf32(v.w);
        }
#pragma unroll
        for (int j = tid; j < 1024; j += 256) {
            int col = j >> 3;
            int kq  = j & 7;
            int c   = bc + col;
            int r   = c >> 6;
            int o   = c & 63;
            float4 v = *reinterpret_cast<const float4*>(
                W + ((size_t)r * OUT_F + o) * IN_F + k0 + kq * 4);
            Bs[kq * 4 + 0][col] = cvt_tf32(v.x);
            Bs[kq * 4 + 1][col] = cvt_tf32(v.y);
            Bs[kq * 4 + 2][col] = cvt_tf32(v.z);
            Bs[kq * 4 + 3][col] = cvt_tf32(v.w);
        }
        __syncthreads();

#pragma unroll
        for (int ks = 0; ks < 4; ks++) {
            const int kb = ks * 8;
            uint32_t af[4][4];
#pragma unroll
            for (int mt = 0; mt < 4; mt++) {
                int row = warp_m + mt * 16 + g;
                af[mt][0] = As[kb + t][row];
                af[mt][1] = As[kb + t][row + 8];
                af[mt][2] = As[kb + t + 4][row];
                af[mt][3] = As[kb + t + 4][row + 8];
            }
            uint32_t bf[4][2];
#pragma unroll
            for (int nt = 0; nt < 4; nt++) {
                int col = warp_n + nt * 8 + g;
                bf[nt][0] = Bs[kb + t][col];
                bf[nt][1] = Bs[kb + t + 4][col];
            }
#pragma unroll
            for (int mt = 0; mt < 4; mt++)
#pragma unroll
                for (int nt = 0; nt < 4; nt++) {
                    asm volatile(
                        "mma.sync.aligned.m16n8k8.row.col.f32.tf32.tf32.f32 "
                        "{%0,%1,%2,%3}, {%4,%5,%6,%7}, {%8,%9}, {%0,%1,%2,%3};"
                        : "+f"(acc[mt][nt][0]), "+f"(acc[mt][nt][1]),
                          "+f"(acc[mt][nt][2]), "+f"(acc[mt][nt][3])
                        : "r"(af[mt][0]), "r"(af[mt][1]), "r"(af[mt][2]), "r"(af[mt][3]),
                          "r"(bf[nt][0]), "r"(bf[nt][1]));
                }
        }
        __syncthreads();
    }

    // Store fp16: c0=C[g][2t] c1=C[g][2t+1] (one half2 = 4B), rows g and g+8.
#pragma unroll
    for (int mt = 0; mt < 4; mt++) {
#pragma unroll
        for (int nt = 0; nt < 4; nt++) {
            int col = bc + warp_n + nt * 8 + t * 2;
            int rel = col >> 6;
            int o   = col & 63;
            int row0 = bm + warp_m + mt * 16 + g;
            if (row0 < N_NODES) {
                __half2* p = reinterpret_cast<__half2*>(
                    g_xw + ((size_t)rel * N_NODES + row0) * OUT_F + o);
                *p = __floats2half2_rn(acc[mt][nt][0], acc[mt][nt][1]);
            }
            int row1 = row0 + 8;
            if (row1 < N_NODES) {
                __half2* p = reinterpret_cast<__half2*>(
                    g_xw + ((size_t)rel * N_NODES + row1) * OUT_F + o);
                *p = __floats2half2_rn(acc[mt][nt][2], acc[mt][nt][3]);
            }
        }
    }
}

// ---------------------------------------------------------------------------
// Reduce: one warp per destination node. Lane l owns output cols 2l, 2l+1
// (one half2 = 4B; warp reads a full 128B row per step). fp32 accumulate.
// ---------------------------------------------------------------------------
__global__ __launch_bounds__(256)
void reduce_kernel(float* __restrict__ out) {
    int warp = (blockIdx.x * 256 + threadIdx.x) >> 5;   // node id, exact cover
    int lane = threadIdx.x & 31;
    int beg = g_off[warp];
    int end = g_off[warp + 1];

    const __half2* xw2 = reinterpret_cast<const __half2*>(g_xw);
    float2 acc = make_float2(0.f, 0.f);
    int j = beg;
    for (; j + 8 <= end; j += 8) {
        float2 v[8];
#pragma unroll
        for (int u = 0; u < 8; u++) {
            int p = g_perm[j + u];
            v[u] = __half22float2(xw2[(size_t)p * (OUT_F / 2) + lane]);
        }
#pragma unroll
        for (int u = 0; u < 8; u++) { acc.x += v[u].x; acc.y += v[u].y; }
    }
    for (; j < end; j++) {
        int p = g_perm[j];
        float2 v = __half22float2(xw2[(size_t)p * (OUT_F / 2) + lane]);
        acc.x += v.x; acc.y += v.y;
    }
    *reinterpret_cast<float2*>(out + (size_t)warp * OUT_F + lane * 2) = acc;
}

extern "C" void kernel_launch(void* const* d_in, const int* in_sizes, int n_in,
                              void* d_out, int out_size) {
    const float* feat = (const float*)d_in[0];
    const float* W    = (const float*)d_in[1];
    const int* esrc   = (const int*)d_in[2];
    const int* edst   = (const int*)d_in[3];
    const int* etyp   = (const int*)d_in[4];
    float* out        = (float*)d_out;

    const int nb_node = (N_NODES + 255) / 256;   // 391
    const int nb_edge = (N_EDGES + 255) / 256;   // 6400

    // CSR build by destination
    init_cnt_kernel<<<nb_node, 256>>>();
    hist_kernel<<<nb_edge, 256>>>(edst);
    scan1_kernel<<<SCAN_BLOCKS, 256>>>();
    scan2_kernel<<<1, 512>>>();
    scan3_kernel<<<SCAN_BLOCKS, 256>>>();
    fill_kernel<<<nb_edge, 256>>>(esrc, edst, etyp);

    // xw[r][n][o] = feat @ W[r]^T via tf32 mma.sync (fp16 store)
    dim3 ggrid((N_NODES + 127) / 128, COLS / 128);
    gemm_mma_kernel<<<ggrid, 256>>>(feat, W);

    // Gather + register reduce per destination node (writes every output elem)
    reduce_kernel<<<(N_NODES * 32) / 256, 256>>>(out);
}

// round 10
// speedup vs baseline: 1.4897x; 1.4561x over previous
#include <cuda_runtime.h>
#include <cuda_fp16.h>
#include <cstdint>

#define N_NODES 100000
#define N_EDGES 1638400
#define IN_F    128
#define OUT_F   64
#define NUM_RELS 8
#define COLS    (NUM_RELS * OUT_F)   // 512
#define SCAN_BLOCKS ((N_NODES + 255) / 256)   // 391

// Scratch: xw[r][n][o] in fp16, layout ((r*N + n)*64 + o). 102.4 MB.
__device__ __half g_xw[(size_t)NUM_RELS * N_NODES * OUT_F];

// CSR-by-destination scratch
__device__ int g_cnt[N_NODES];
__device__ int g_off[N_NODES + 1];
__device__ int g_cursor[N_NODES];
__device__ int g_bsum[512];
__device__ int g_perm[N_EDGES];     // packed rel*N_NODES + src, grouped by dst

// ---------------------------------------------------------------------------
// CSR build: zero counters -> histogram -> 3-step scan -> fill
// ---------------------------------------------------------------------------
__global__ void init_cnt_kernel() {
    int i = blockIdx.x * blockDim.x + threadIdx.x;
    if (i < N_NODES) g_cnt[i] = 0;
}

__global__ void hist_kernel(const int* __restrict__ edst) {
    int e = blockIdx.x * blockDim.x + threadIdx.x;
    if (e < N_EDGES) atomicAdd(&g_cnt[edst[e]], 1);
}

__global__ void scan1_kernel() {
    __shared__ int s[256];
    int tid = threadIdx.x;
    int i = blockIdx.x * 256 + tid;
    int v = (i < N_NODES) ? g_cnt[i] : 0;
    s[tid] = v;
    __syncthreads();
#pragma unroll
    for (int d = 1; d < 256; d <<= 1) {
        int t = (tid >= d) ? s[tid - d] : 0;
        __syncthreads();
        s[tid] += t;
        __syncthreads();
    }
    if (i < N_NODES) g_off[i] = s[tid] - v;      // block-local exclusive
    if (tid == 255) g_bsum[blockIdx.x] = s[255];
}

__global__ void scan2_kernel() {
    __shared__ int s[512];
    int tid = threadIdx.x;
    int v = (tid < SCAN_BLOCKS) ? g_bsum[tid] : 0;
    s[tid] = v;
    __syncthreads();
#pragma unroll
    for (int d = 1; d < 512; d <<= 1) {
        int t = (tid >= d) ? s[tid - d] : 0;
        __syncthreads();
        s[tid] += t;
        __syncthreads();
    }
    if (tid < SCAN_BLOCKS) g_bsum[tid] = s[tid] - v;   // exclusive
}

__global__ void scan3_kernel() {
    int i = blockIdx.x * 256 + threadIdx.x;
    if (i < N_NODES) {
        int o = g_off[i] + g_bsum[blockIdx.x];
        g_off[i] = o;
        g_cursor[i] = o;
    }
    if (i == 0) g_off[N_NODES] = N_EDGES;
}

__global__ void fill_kernel(const int* __restrict__ esrc,
                            const int* __restrict__ edst,
                            const int* __restrict__ etyp) {
    int e = blockIdx.x * blockDim.x + threadIdx.x;
    if (e < N_EDGES) {
        int d = edst[e];
        int pos = atomicAdd(&g_cursor[d], 1);
        g_perm[pos] = etyp[e] * N_NODES + esrc[e];
    }
}

// ---------------------------------------------------------------------------
// fp16 mma.sync GEMM: C[n][c] = sum_k feat[n][k] * W[r][o][k], c = r*64+o.
// CTA tile 128x128, BK=32, 256 threads = 8 warps (2 x 4), warp tile 64x32.
// m16n8k16 f16 HMMA, fp32 accumulate, fp16 epilogue store.
// SMEM: row-major halves, stride 40 (80B) -> conflict-free fragment loads.
// ---------------------------------------------------------------------------
#define APAD 40
__global__ __launch_bounds__(256, 2)
void gemm_mma_kernel(const float* __restrict__ feat, const float* __restrict__ W) {
    __shared__ __half As[128][APAD];   // [row][k]
    __shared__ __half Bs[128][APAD];   // [col][k]

    const int bm = blockIdx.x * 128;
    const int bc = blockIdx.y * 128;
    const int tid = threadIdx.x;
    const int wid = tid >> 5;
    const int lane = tid & 31;
    const int g = lane >> 2;          // 0..7
    const int t = lane & 3;           // 0..3
    const int warp_m = (wid & 1) * 64;
    const int warp_n = (wid >> 1) * 32;

    float acc[4][4][4];
#pragma unroll
    for (int i = 0; i < 4; i++)
#pragma unroll
        for (int j = 0; j < 4; j++)
#pragma unroll
            for (int c = 0; c < 4; c++) acc[i][j][c] = 0.f;

    for (int k0 = 0; k0 < IN_F; k0 += 32) {
        // Load A tile: 128 rows x 32 k = 1024 float4 -> 4 halves each.
#pragma unroll
        for (int j = tid; j < 1024; j += 256) {
            int row = j >> 3;
            int kq  = j & 7;
            int n   = bm + row;
            float4 v = make_float4(0.f, 0.f, 0.f, 0.f);
            if (n < N_NODES)
                v = *reinterpret_cast<const float4*>(feat + (size_t)n * IN_F + k0 + kq * 4);
            __half2* p = reinterpret_cast<__half2*>(&As[row][kq * 4]);
            p[0] = __floats2half2_rn(v.x, v.y);
            p[1] = __floats2half2_rn(v.z, v.w);
        }
        // Load B tile: 128 cols x 32 k. B[col][k] = W[r][o][k0+k].
#pragma unroll
        for (int j = tid; j < 1024; j += 256) {
            int col = j >> 3;
            int kq  = j & 7;
            int c   = bc + col;
            int r   = c >> 6;
            int o   = c & 63;
            float4 v = *reinterpret_cast<const float4*>(
                W + ((size_t)r * OUT_F + o) * IN_F + k0 + kq * 4);
            __half2* p = reinterpret_cast<__half2*>(&Bs[col][kq * 4]);
            p[0] = __floats2half2_rn(v.x, v.y);
            p[1] = __floats2half2_rn(v.z, v.w);
        }
        __syncthreads();

#pragma unroll
        for (int ks = 0; ks < 2; ks++) {
            const int kb = ks * 16;
            // A fragments: {a0,a1}=(row g, k 2t..2t+1), {a2,a3}=(row g+8, same),
            // {a4,a5}=(row g, k 2t+8..9), {a6,a7}=(row g+8, k 2t+8..9)
            uint32_t af[4][4];
#pragma unroll
            for (int mt = 0; mt < 4; mt++) {
                int row = warp_m + mt * 16 + g;
                af[mt][0] = *reinterpret_cast<const uint32_t*>(&As[row][kb + 2 * t]);
                af[mt][1] = *reinterpret_cast<const uint32_t*>(&As[row + 8][kb + 2 * t]);
                af[mt][2] = *reinterpret_cast<const uint32_t*>(&As[row][kb + 2 * t + 8]);
                af[mt][3] = *reinterpret_cast<const uint32_t*>(&As[row + 8][kb + 2 * t + 8]);
            }
            // B fragments: {b0,b1}=(k 2t..2t+1, col g), {b2,b3}=(k 2t+8..9, col g)
            uint32_t bf[4][2];
#pragma unroll
            for (int nt = 0; nt < 4; nt++) {
                int col = warp_n + nt * 8 + g;
                bf[nt][0] = *reinterpret_cast<const uint32_t*>(&Bs[col][kb + 2 * t]);
                bf[nt][1] = *reinterpret_cast<const uint32_t*>(&Bs[col][kb + 2 * t + 8]);
            }
#pragma unroll
            for (int mt = 0; mt < 4; mt++)
#pragma unroll
                for (int nt = 0; nt < 4; nt++) {
                    asm volatile(
                        "mma.sync.aligned.m16n8k16.row.col.f32.f16.f16.f32 "
                        "{%0,%1,%2,%3}, {%4,%5,%6,%7}, {%8,%9}, {%0,%1,%2,%3};"
                        : "+f"(acc[mt][nt][0]), "+f"(acc[mt][nt][1]),
                          "+f"(acc[mt][nt][2]), "+f"(acc[mt][nt][3])
                        : "r"(af[mt][0]), "r"(af[mt][1]), "r"(af[mt][2]), "r"(af[mt][3]),
                          "r"(bf[nt][0]), "r"(bf[nt][1]));
                }
        }
        __syncthreads();
    }

    // Store fp16: c0=C[g][2t] c1=C[g][2t+1] (one half2 = 4B), rows g and g+8.
#pragma unroll
    for (int mt = 0; mt < 4; mt++) {
#pragma unroll
        for (int nt = 0; nt < 4; nt++) {
            int col = bc + warp_n + nt * 8 + t * 2;
            int rel = col >> 6;
            int o   = col & 63;
            int row0 = bm + warp_m + mt * 16 + g;
            if (row0 < N_NODES) {
                __half2* p = reinterpret_cast<__half2*>(
                    g_xw + ((size_t)rel * N_NODES + row0) * OUT_F + o);
                *p = __floats2half2_rn(acc[mt][nt][0], acc[mt][nt][1]);
            }
            int row1 = row0 + 8;
            if (row1 < N_NODES) {
                __half2* p = reinterpret_cast<__half2*>(
                    g_xw + ((size_t)rel * N_NODES + row1) * OUT_F + o);
                *p = __floats2half2_rn(acc[mt][nt][2], acc[mt][nt][3]);
            }
        }
    }
}

// ---------------------------------------------------------------------------
// Reduce: one warp per destination node. Lane l owns output cols 2l, 2l+1
// (one half2 = 4B; warp reads a full 128B row per step). fp32 accumulate.
// ---------------------------------------------------------------------------
__global__ __launch_bounds__(256)
void reduce_kernel(float* __restrict__ out) {
    int warp = (blockIdx.x * 256 + threadIdx.x) >> 5;   // node id, exact cover
    int lane = threadIdx.x & 31;
    int beg = g_off[warp];
    int end = g_off[warp + 1];

    const __half2* xw2 = reinterpret_cast<const __half2*>(g_xw);
    float2 acc = make_float2(0.f, 0.f);
    int j = beg;
    for (; j + 8 <= end; j += 8) {
        float2 v[8];
#pragma unroll
        for (int u = 0; u < 8; u++) {
            int p = g_perm[j + u];
            v[u] = __half22float2(xw2[(size_t)p * (OUT_F / 2) + lane]);
        }
#pragma unroll
        for (int u = 0; u < 8; u++) { acc.x += v[u].x; acc.y += v[u].y; }
    }
    for (; j < end; j++) {
        int p = g_perm[j];
        float2 v = __half22float2(xw2[(size_t)p * (OUT_F / 2) + lane]);
        acc.x += v.x; acc.y += v.y;
    }
    *reinterpret_cast<float2*>(out + (size_t)warp * OUT_F + lane * 2) = acc;
}

extern "C" void kernel_launch(void* const* d_in, const int* in_sizes, int n_in,
                              void* d_out, int out_size) {
    const float* feat = (const float*)d_in[0];
    const float* W    = (const float*)d_in[1];
    const int* esrc   = (const int*)d_in[2];
    const int* edst   = (const int*)d_in[3];
    const int* etyp   = (const int*)d_in[4];
    float* out        = (float*)d_out;

    const int nb_node = (N_NODES + 255) / 256;   // 391
    const int nb_edge = (N_EDGES + 255) / 256;   // 6400

    // CSR build by destination
    init_cnt_kernel<<<nb_node, 256>>>();
    hist_kernel<<<nb_edge, 256>>>(edst);
    scan1_kernel<<<SCAN_BLOCKS, 256>>>();
    scan2_kernel<<<1, 512>>>();
    scan3_kernel<<<SCAN_BLOCKS, 256>>>();
    fill_kernel<<<nb_edge, 256>>>(esrc, edst, etyp);

    // xw[r][n][o] = feat @ W[r]^T via fp16 mma.sync (fp32 accum, fp16 store)
    dim3 ggrid((N_NODES + 127) / 128, COLS / 128);
    gemm_mma_kernel<<<ggrid, 256>>>(feat, W);

    // Gather + register reduce per destination node (writes every output elem)
    reduce_kernel<<<(N_NODES * 32) / 256, 256>>>(out);
}